// round 15
// baseline (speedup 1.0000x reference)
#include <cuda_runtime.h>
#include <math.h>

typedef unsigned long long u64;

// ---------------- problem constants ----------------
#define BATCH 4096
#define NROI  90
#define TLEN  195
#define HID   20
#define FLATD (NROI*HID)     // 1800
#define KPAD  1824           // FLATD padded to multiple of 32
#define D1    512
#define D2    256
#define EPSBN 1e-5f

#define TQ   49              // ceil(195/4)
#define XST  364             // floats per tq-row: 91 rows * 4

// ---------------- packed-fp32 helpers (Blackwell f32x2 pipe) ----------------
__device__ __forceinline__ void fma2(u64& d, u64 a, u64 b) {
    asm("fma.rn.f32x2 %0, %1, %2, %0;" : "+l"(d) : "l"(a), "l"(b));
}
__device__ __forceinline__ u64 splat2(float a) {
    u64 r; asm("mov.b64 %0, {%1, %1};" : "=l"(r) : "f"(a)); return r;
}
__device__ __forceinline__ float2 u2f(u64 v) {
    float2 f; asm("mov.b64 {%0, %1}, %2;" : "=f"(f.x), "=f"(f.y) : "l"(v)); return f;
}

// gram tiles: 12 upper-triangle 32x16 tiles (i-strips {0,32,64}, j-tiles 16)
__constant__ int c_si[12] = {0,0,0,0,0,0, 32,32,32,32, 64,64};
__constant__ int c_sj[12] = {0,16,32,48,64,80, 32,48,64,80, 64,80};

// ---------------- scratch (device globals; no allocs) ----------------
__device__ float g_flat[(size_t)BATCH * KPAD];
__device__ float g_w1p[(size_t)KPAD * D1];     // padded l1_w
__device__ float g_w1q[196 * HID];             // gc1_w with zero pad row
__device__ float g_z1[(size_t)BATCH * D1];
__device__ float g_z2[(size_t)BATCH * D2];
__device__ float g_s1[D1];
__device__ float g_t1[D1];
__device__ float g_s2[D2];
__device__ float g_t2[D2];
__device__ float g_ps1[64 * D1];               // per-rowblock col sums
__device__ float g_pq1[64 * D1];
__device__ float g_ps2[64 * D2];
__device__ float g_pq2[64 * D2];

// smem layout (floats): xs | adj/w1 (overlapped) | buf | w2 | mu | rd
#define SM_XS    (TQ * XST)            // 17836
#define SM_ADJ   (NROI * 92)           // 8280 (>= 3920 for w1)
#define SM_BUF   (NROI * HID)          // 1800
#define SM_W2    (HID * HID)           // 400
#define SM_TOTAL (SM_XS + SM_ADJ + SM_BUF + SM_W2 + 96 + 96)   // 28508 fl = 114032 B

// ============================================================================
// Prep kernels (2 launches; keep GEMM1 in the ncu capture slot #4)
// ============================================================================
__global__ void prep_a(const float* __restrict__ w1) {
    int i = blockIdx.x * 256 + threadIdx.x;
    if (i < 196 * HID) g_w1q[i] = (i < TLEN * HID) ? w1[i] : 0.0f;
}
__global__ void prep_b(const float* __restrict__ l1w) {
    int i = blockIdx.x * 256 + threadIdx.x;
    const int NW = KPAD * D1 / 4;                  // 233472 float4 of w1p
    if (i < NW) {
        int row = i / (D1 / 4);
        float4 v = make_float4(0.f, 0.f, 0.f, 0.f);
        if (row < FLATD) v = ((const float4*)l1w)[i];
        ((float4*)g_w1p)[i] = v;
    } else {
        int j = i - NW;                            // flat pad zeros
        if (j < BATCH * (KPAD - FLATD)) {
            int b = j / (KPAD - FLATD);
            int c = j - b * (KPAD - FLATD);
            g_flat[(size_t)b * KPAD + FLATD + c] = 0.0f;
        }
    }
}

// ============================================================================
// Kernel: per-sample fused GCN -> g_flat   (2 CTAs/SM; R12/R14 measured-best)
// ============================================================================
__global__ void __launch_bounds__(512, 2)
gcn_kernel(const float* __restrict__ input,
           const float* __restrict__ w2)   // [20,20]
{
    extern __shared__ float sm[];
    float* xs  = sm;                       // packed x: xs[tq*364 + r*4 + comp]
    float* adj = xs  + SM_XS;              // gram/adj; FIRST used as w1 staging
    float* w1s = adj;                      // alias (w1 read before gram writes)
    float* buf = adj + SM_ADJ;             // xw, then hw
    float* w2s = buf + SM_BUF;
    float* mu  = w2s + SM_W2;              // [96]
    float* rd  = mu  + 96;                 // [96]

    const int tid  = threadIdx.x;
    const int b    = blockIdx.x;
    const int w    = tid >> 5;
    const int lane = tid & 31;

    // ---- zero the t=195 pad component for ROI rows ----
    if (tid < NROI) xs[48 * XST + tid * 4 + 3] = 0.0f;

    // ---- load x (coalesced), w1 (into adj region), w2 ----
    const float* xin = input + (size_t)b * (NROI * TLEN);
    for (int idx = tid; idx < NROI * TLEN; idx += 512) {
        int r = idx / TLEN;
        int t = idx - r * TLEN;
        xs[(t >> 2) * XST + r * 4 + (t & 3)] = xin[idx];
    }
    for (int i = tid; i < 196 * HID; i += 512) w1s[i] = g_w1q[i];
    if (tid < SM_W2) w2s[tid] = w2[tid];
    __syncthreads();

    // ---- phase A: row means + diag rsqrt + xw = x @ w1 (all read xs only) ----
    const int r3 = lane / 10;              // 0..2 (lanes 30,31 idle)
    const int hp = lane - r3 * 10;         // 0..9
    const bool act = (w < 15) && (lane < 30);

    if (w < 15) {
        for (int i = w * 6; i < w * 6 + 6; ++i) {
            float s = 0.0f, q = 0.0f;
            for (int t = lane; t < TLEN; t += 32) {
                float x = xs[(t >> 2) * XST + i * 4 + (t & 3)];
                s += x; q += x * x;
            }
            #pragma unroll
            for (int o = 16; o; o >>= 1) {
                s += __shfl_xor_sync(0xffffffffu, s, o);
                q += __shfl_xor_sync(0xffffffffu, q, o);
            }
            if (lane == 0) {
                mu[i] = s * (1.0f / (float)TLEN);
                rd[i] = rsqrtf(q - s * s * (1.0f / (float)TLEN));
            }
        }
    }
    if (act) {
        const int r0 = w * 6 + r3;
        u64 acc0 = 0ull, acc1 = 0ull;
        for (int tq = 0; tq < TQ; ++tq) {
            float4 xA = ((const float4*)(xs + tq * XST))[r0];
            float4 xB = ((const float4*)(xs + tq * XST))[r0 + 3];
            const float* wr = &w1s[tq * 80 + 2 * hp];
            u64 w0 = *(const u64*)&wr[0];
            u64 w1v = *(const u64*)&wr[20];
            u64 w2v = *(const u64*)&wr[40];
            u64 w3v = *(const u64*)&wr[60];
            fma2(acc0, splat2(xA.x), w0);  fma2(acc0, splat2(xA.y), w1v);
            fma2(acc0, splat2(xA.z), w2v); fma2(acc0, splat2(xA.w), w3v);
            fma2(acc1, splat2(xB.x), w0);  fma2(acc1, splat2(xB.y), w1v);
            fma2(acc1, splat2(xB.z), w2v); fma2(acc1, splat2(xB.w), w3v);
        }
        *(u64*)&buf[r0 * HID + 2 * hp]       = acc0;
        *(u64*)&buf[(r0 + 3) * HID + 2 * hp] = acc1;
    }
    __syncthreads();   // w1 reads done; mu/rd ready; gram may overwrite adj

    // ---- symmetric gram + fused corrcoef normalize: 12 tiles of 32x16 ----
    if (w < 12) {
        const int ii = lane >> 2;   // 0..7
        const int jj = lane & 3;    // 0..3
        const int si = c_si[w], sj = c_sj[w];
        u64 acc[4][4];
        #pragma unroll
        for (int k = 0; k < 4; k++)
            #pragma unroll
            for (int c = 0; c < 4; c++) acc[k][c] = 0ull;

        for (int tq = 0; tq < TQ; ++tq) {
            const ulonglong2* row = (const ulonglong2*)(xs + tq * XST);
            ulonglong2 b0 = row[sj + jj];
            ulonglong2 b1 = row[sj + jj + 4];
            ulonglong2 b2 = row[sj + jj + 8];
            ulonglong2 b3 = row[sj + jj + 12];
            #pragma unroll
            for (int k = 0; k < 4; k++) {
                ulonglong2 a = row[si + ii + 8 * k];
                fma2(acc[k][0], a.x, b0.x); fma2(acc[k][0], a.y, b0.y);
                fma2(acc[k][1], a.x, b1.x); fma2(acc[k][1], a.y, b1.y);
                fma2(acc[k][2], a.x, b2.x); fma2(acc[k][2], a.y, b2.y);
                fma2(acc[k][3], a.x, b3.x); fma2(acc[k][3], a.y, b3.y);
            }
        }
        // epilogue: normalize + clip + mirrored store
        float muj[4], rdj[4];
        #pragma unroll
        for (int c = 0; c < 4; c++) {
            int j = sj + jj + 4 * c;
            muj[c] = mu[j] * (float)TLEN;
            rdj[c] = rd[j];
        }
        #pragma unroll
        for (int k = 0; k < 4; k++) {
            int i = si + ii + 8 * k;
            if (i < NROI) {
                float mui = mu[i], rdi = rd[i];
                #pragma unroll
                for (int c = 0; c < 4; c++) {
                    int j = sj + jj + 4 * c;
                    if (j < NROI) {
                        float2 v = u2f(acc[k][c]);
                        float g = (v.x + v.y - mui * muj[c]) * rdi * rdj[c];
                        g = fminf(1.0f, fmaxf(-1.0f, g));
                        adj[i * 92 + j] = g;
                        adj[j * 92 + i] = g;
                    }
                }
            }
        }
    }
    __syncthreads();

    // ---- h1 = adj @ xw (into registers) ----
    u64 h1a = 0ull, h1b = 0ull;
    if (act) {
        const int n0 = w * 6 + r3;
        const float* ar0 = &adj[n0 * 92];
        const float* ar1 = &adj[(n0 + 3) * 92];
        #pragma unroll 5
        for (int m = 0; m < NROI; m += 2) {
            u64 xv0 = *(const u64*)&buf[m * HID + 2 * hp];
            u64 xv1 = *(const u64*)&buf[(m + 1) * HID + 2 * hp];
            float2 a = *(const float2*)&ar0[m];
            float2 c = *(const float2*)&ar1[m];
            fma2(h1a, splat2(a.x), xv0); fma2(h1a, splat2(a.y), xv1);
            fma2(h1b, splat2(c.x), xv0); fma2(h1b, splat2(c.y), xv1);
        }
    }
    __syncthreads();   // all xw reads done; buf can be overwritten with hw

    // ---- hw = h1 @ w2 (h1 gathered via warp shuffle) -> buf ----
    {
        u64 hw0 = 0ull, hw1 = 0ull;
        const int base = r3 * 10;
        #pragma unroll
        for (int kk = 0; kk < 10; ++kk) {
            u64 p0 = __shfl_sync(0xffffffffu, h1a, base + kk);
            u64 p1 = __shfl_sync(0xffffffffu, h1b, base + kk);
            float2 f0 = u2f(p0);
            float2 f1 = u2f(p1);
            u64 wva = *(const u64*)&w2s[(2 * kk) * HID + 2 * hp];
            u64 wvb = *(const u64*)&w2s[(2 * kk + 1) * HID + 2 * hp];
            fma2(hw0, splat2(f0.x), wva); fma2(hw0, splat2(f0.y), wvb);
            fma2(hw1, splat2(f1.x), wva); fma2(hw1, splat2(f1.y), wvb);
        }
        if (act) {
            const int n0 = w * 6 + r3;
            *(u64*)&buf[n0 * HID + 2 * hp]       = hw0;
            *(u64*)&buf[(n0 + 3) * HID + 2 * hp] = hw1;
        }
    }
    __syncthreads();

    // ---- h2 = adj @ hw -> global flat ----
    if (act) {
        const int n0 = w * 6 + r3;
        u64 acc0 = 0ull, acc1 = 0ull;
        const float* ar0 = &adj[n0 * 92];
        const float* ar1 = &adj[(n0 + 3) * 92];
        #pragma unroll 5
        for (int m = 0; m < NROI; m += 2) {
            u64 xv0 = *(const u64*)&buf[m * HID + 2 * hp];
            u64 xv1 = *(const u64*)&buf[(m + 1) * HID + 2 * hp];
            float2 a = *(const float2*)&ar0[m];
            float2 c = *(const float2*)&ar1[m];
            fma2(acc0, splat2(a.x), xv0); fma2(acc0, splat2(a.y), xv1);
            fma2(acc1, splat2(c.x), xv0); fma2(acc1, splat2(c.y), xv1);
        }
        float* dst = g_flat + (size_t)b * KPAD;
        *(u64*)&dst[n0 * HID + 2 * hp]       = acc0;
        *(u64*)&dst[(n0 + 3) * HID + 2 * hp] = acc1;
    }
}

// ============================================================================
// GEMM: BM=64 x BN=64 x BK=16, TM=16 (8 row-pairs), TN=4, 64 threads,
// double-buffered.  C = A' @ W + bias (A' = A*scale+shift if scale != null).
// Per kk: 5 LDS.128 + 4 splats + 32 fma2  (issue eff ~70%).
// Epilogue: per-rowblock column sum/sumsq partials.
// ============================================================================
__global__ void __launch_bounds__(64)
sgemm_fused(const float* __restrict__ A, const float* __restrict__ W,
            const float* __restrict__ bias,
            const float* __restrict__ scale, const float* __restrict__ shift,
            float* __restrict__ C,
            float* __restrict__ psum, float* __restrict__ psq,
            int M, int K, int N)
{
    constexpr int BM = 64, BN = 64, BK = 16, THREADS = 64;
    constexpr int TYS = 4;                       // BM/16
    constexpr int AF4 = BM * BK / 4 / THREADS;   // 4
    constexpr int WF4 = BK * BN / 4 / THREADS;   // 4
    __shared__ float As[2][BK][BM + 4];
    __shared__ float Bs[2][BK][BN];

    const int tid = threadIdx.x;
    const int tx  = tid % 16;                    // 0..15 (n / 4)
    const int ty  = tid / 16;                    // 0..3  (m / 16)
    const int bm  = blockIdx.y * BM;
    const int bn  = blockIdx.x * BN;

    float4 areg[AF4], wreg[WF4];

    auto ldg_tiles = [&](int k0) {
        #pragma unroll
        for (int t = 0; t < AF4; t++) {
            int i  = tid + t * THREADS;
            int r  = i / (BK / 4);
            int c4 = (i % (BK / 4)) * 4;
            float4 v = *(const float4*)&A[(size_t)(bm + r) * K + k0 + c4];
            if (scale) {
                float4 sc = *(const float4*)&scale[k0 + c4];
                float4 sh = *(const float4*)&shift[k0 + c4];
                v.x = v.x * sc.x + sh.x; v.y = v.y * sc.y + sh.y;
                v.z = v.z * sc.z + sh.z; v.w = v.w * sc.w + sh.w;
            }
            areg[t] = v;
        }
        #pragma unroll
        for (int t = 0; t < WF4; t++) {
            int i  = tid + t * THREADS;
            int r  = i / (BN / 4);
            int c4 = (i % (BN / 4)) * 4;
            wreg[t] = *(const float4*)&W[(size_t)(k0 + r) * N + bn + c4];
        }
    };
    auto sts_tiles = [&](int s) {
        #pragma unroll
        for (int t = 0; t < AF4; t++) {
            int i  = tid + t * THREADS;
            int r  = i / (BK / 4);
            int c4 = (i % (BK / 4)) * 4;
            As[s][c4 + 0][r] = areg[t].x; As[s][c4 + 1][r] = areg[t].y;
            As[s][c4 + 2][r] = areg[t].z; As[s][c4 + 3][r] = areg[t].w;
        }
        #pragma unroll
        for (int t = 0; t < WF4; t++) {
            int i  = tid + t * THREADS;
            int r  = i / (BN / 4);
            int c4 = (i % (BN / 4)) * 4;
            *(float4*)&Bs[s][r][c4] = wreg[t];
        }
    };

    u64 acc[8][4];
    #pragma unroll
    for (int p = 0; p < 8; p++)
        #pragma unroll
        for (int j = 0; j < 4; j++) acc[p][j] = 0ull;

    ldg_tiles(0);
    sts_tiles(0);
    __syncthreads();

    const int nit = K / BK;
    for (int it = 0; it < nit; ++it) {
        const int cur = it & 1;
        if (it + 1 < nit) ldg_tiles((it + 1) * BK);

        #pragma unroll
        for (int kk = 0; kk < BK; kk++) {
            const float* arow = &As[cur][kk][ty * 16];
            u64 a0 = *(const u64*)&arow[0];
            u64 a1 = *(const u64*)&arow[2];
            u64 a2 = *(const u64*)&arow[4];
            u64 a3 = *(const u64*)&arow[6];
            u64 a4 = *(const u64*)&arow[8];
            u64 a5 = *(const u64*)&arow[10];
            u64 a6 = *(const u64*)&arow[12];
            u64 a7 = *(const u64*)&arow[14];
            float4 bv = *(const float4*)&Bs[cur][kk][tx * 4];
            u64 b0 = splat2(bv.x), b1 = splat2(bv.y);
            u64 b2 = splat2(bv.z), b3 = splat2(bv.w);
            fma2(acc[0][0], a0, b0); fma2(acc[1][0], a1, b0);
            fma2(acc[2][0], a2, b0); fma2(acc[3][0], a3, b0);
            fma2(acc[4][0], a4, b0); fma2(acc[5][0], a5, b0);
            fma2(acc[6][0], a6, b0); fma2(acc[7][0], a7, b0);
            fma2(acc[0][1], a0, b1); fma2(acc[1][1], a1, b1);
            fma2(acc[2][1], a2, b1); fma2(acc[3][1], a3, b1);
            fma2(acc[4][1], a4, b1); fma2(acc[5][1], a5, b1);
            fma2(acc[6][1], a6, b1); fma2(acc[7][1], a7, b1);
            fma2(acc[0][2], a0, b2); fma2(acc[1][2], a1, b2);
            fma2(acc[2][2], a2, b2); fma2(acc[3][2], a3, b2);
            fma2(acc[4][2], a4, b2); fma2(acc[5][2], a5, b2);
            fma2(acc[6][2], a6, b2); fma2(acc[7][2], a7, b2);
            fma2(acc[0][3], a0, b3); fma2(acc[1][3], a1, b3);
            fma2(acc[2][3], a2, b3); fma2(acc[3][3], a3, b3);
            fma2(acc[4][3], a4, b3); fma2(acc[5][3], a5, b3);
            fma2(acc[6][3], a6, b3); fma2(acc[7][3], a7, b3);
        }
        if (it + 1 < nit) sts_tiles(cur ^ 1);
        __syncthreads();
    }

    float4 bias4 = *(const float4*)&bias[bn + tx * 4];
    float cs[4] = {0.f, 0.f, 0.f, 0.f};
    float cq[4] = {0.f, 0.f, 0.f, 0.f};
    #pragma unroll
    for (int p = 0; p < 8; p++) {
        float2 c0 = u2f(acc[p][0]);
        float2 c1 = u2f(acc[p][1]);
        float2 c2 = u2f(acc[p][2]);
        float2 c3 = u2f(acc[p][3]);
        int row = bm + ty * 16 + 2 * p;
        float4 lo = make_float4(c0.x + bias4.x, c1.x + bias4.y, c2.x + bias4.z, c3.x + bias4.w);
        float4 hi = make_float4(c0.y + bias4.x, c1.y + bias4.y, c2.y + bias4.z, c3.y + bias4.w);
        *(float4*)&C[(size_t)row * N + bn + tx * 4]       = lo;
        *(float4*)&C[(size_t)(row + 1) * N + bn + tx * 4] = hi;
        cs[0] += lo.x + hi.x;  cq[0] += lo.x * lo.x + hi.x * hi.x;
        cs[1] += lo.y + hi.y;  cq[1] += lo.y * lo.y + hi.y * hi.y;
        cs[2] += lo.z + hi.z;  cq[2] += lo.z * lo.z + hi.z * hi.z;
        cs[3] += lo.w + hi.w;  cq[3] += lo.w * lo.w + hi.w * hi.w;
    }

    // ---- in-CTA column reduction over ty (reuse Bs as scratch) ----
    float* rs = (float*)Bs;          // [TYS][BN]
    float* rq = rs + TYS * BN;
    const int cb = tx * 4;
    __syncthreads();
    #pragma unroll
    for (int j = 0; j < 4; j++) {
        rs[ty * BN + cb + j] = cs[j];
        rq[ty * BN + cb + j] = cq[j];
    }
    __syncthreads();
    #pragma unroll
    for (int o = TYS / 2; o; o >>= 1) {
        if (ty < o) {
            #pragma unroll
            for (int j = 0; j < 4; j++) {
                rs[ty * BN + cb + j] += rs[(ty + o) * BN + cb + j];
                rq[ty * BN + cb + j] += rq[(ty + o) * BN + cb + j];
            }
        }
        __syncthreads();
    }
    if (ty == 0) {
        #pragma unroll
        for (int j = 0; j < 4; j++) {
            psum[(size_t)blockIdx.y * N + bn + cb + j] = rs[cb + j];
            psq [(size_t)blockIdx.y * N + bn + cb + j] = rq[cb + j];
        }
    }
}

// ============================================================================
// bn_final: fold per-rowblock partials into scale/shift
// ============================================================================
__global__ void bn_final(const float* __restrict__ psum, const float* __restrict__ psq,
                         int nparts, int N,
                         const float* __restrict__ gamma, const float* __restrict__ beta,
                         float* __restrict__ s, float* __restrict__ t)
{
    int col = blockIdx.x * 128 + threadIdx.x;
    if (col >= N) return;
    float a = 0.0f, q = 0.0f;
    for (int i = 0; i < nparts; ++i) {
        a += psum[(size_t)i * N + col];
        q += psq[(size_t)i * N + col];
    }
    float mean = a * (1.0f / (float)BATCH);
    float var  = q * (1.0f / (float)BATCH) - mean * mean;
    float sc   = gamma[col] * rsqrtf(var + EPSBN);
    s[col] = sc;
    t[col] = beta[col] - mean * sc;
}

// ============================================================================
// head — BN2-apply + [256,2] linear + softmax, warp per row
// ============================================================================
__global__ void head_kernel(const float* __restrict__ Z,
                            const float* __restrict__ s, const float* __restrict__ t,
                            const float* __restrict__ W3, const float* __restrict__ b3,
                            float* __restrict__ out)
{
    const int warp = threadIdx.x >> 5;
    const int lane = threadIdx.x & 31;
    const int row  = blockIdx.x * 8 + warp;
    const float* z = Z + (size_t)row * D2;
    float a0 = 0.0f, a1 = 0.0f;
    for (int k = lane; k < D2; k += 32) {
        float v = z[k] * s[k] + t[k];
        a0 += v * W3[k * 2 + 0];
        a1 += v * W3[k * 2 + 1];
    }
    #pragma unroll
    for (int o = 16; o; o >>= 1) {
        a0 += __shfl_xor_sync(0xffffffffu, a0, o);
        a1 += __shfl_xor_sync(0xffffffffu, a1, o);
    }
    if (lane == 0) {
        a0 += b3[0];
        a1 += b3[1];
        float m  = fmaxf(a0, a1);
        float e0 = expf(a0 - m);
        float e1 = expf(a1 - m);
        float inv = 1.0f / (e0 + e1);
        out[row * 2 + 0] = e0 * inv;
        out[row * 2 + 1] = e1 * inv;
    }
}

// ============================================================================
// launch
// ============================================================================
extern "C" void kernel_launch(void* const* d_in, const int* in_sizes, int n_in,
                              void* d_out, int out_size)
{
    const float* input = (const float*)d_in[0];
    const float* gc1_w = (const float*)d_in[1];
    const float* gc2_w = (const float*)d_in[2];
    const float* l1_w  = (const float*)d_in[3];
    const float* l1_b  = (const float*)d_in[4];
    const float* bn1_g = (const float*)d_in[5];
    const float* bn1_b = (const float*)d_in[6];
    const float* l2_w  = (const float*)d_in[7];
    const float* l2_b  = (const float*)d_in[8];
    const float* bn2_g = (const float*)d_in[9];
    const float* bn2_b = (const float*)d_in[10];
    const float* l3_w  = (const float*)d_in[11];
    const float* l3_b  = (const float*)d_in[12];
    float* out = (float*)d_out;

    float *flat, *w1p, *z1, *z2, *s1, *t1, *s2, *t2;
    float *ps1, *pq1, *ps2, *pq2;
    cudaGetSymbolAddress((void**)&flat, g_flat);
    cudaGetSymbolAddress((void**)&w1p,  g_w1p);
    cudaGetSymbolAddress((void**)&z1,   g_z1);
    cudaGetSymbolAddress((void**)&z2,   g_z2);
    cudaGetSymbolAddress((void**)&s1,   g_s1);
    cudaGetSymbolAddress((void**)&t1,   g_t1);
    cudaGetSymbolAddress((void**)&s2,   g_s2);
    cudaGetSymbolAddress((void**)&t2,   g_t2);
    cudaGetSymbolAddress((void**)&ps1,  g_ps1);
    cudaGetSymbolAddress((void**)&pq1,  g_pq1);
    cudaGetSymbolAddress((void**)&ps2,  g_ps2);
    cudaGetSymbolAddress((void**)&pq2,  g_pq2);

    const size_t smem = (size_t)SM_TOTAL * sizeof(float);   // 114,032 B
    cudaFuncSetAttribute(gcn_kernel, cudaFuncAttributeMaxDynamicSharedMemorySize, (int)smem);

    // preps (2 launches; GEMM1 stays in ncu capture slot #4)
    prep_a<<<(196 * HID + 255) / 256, 256>>>(gc1_w);
    {
        int total = KPAD * D1 / 4 + BATCH * (KPAD - FLATD);
        prep_b<<<(total + 255) / 256, 256>>>(l1_w);
    }

    // 3. fused GCN -> g_flat [4096,1824]
    gcn_kernel<<<BATCH, 512, smem>>>(input, gc2_w);

    // 4. z1 = flat @ w1p + l1_b + BN1 partials  (TM=16 GEMM, grid 512)
    sgemm_fused<<<dim3(D1 / 64, BATCH / 64), 64>>>(
        flat, w1p, l1_b, nullptr, nullptr, z1, ps1, pq1, BATCH, KPAD, D1);

    // 5. fold BN1 partials -> s1,t1
    bn_final<<<D1 / 128, 128>>>(ps1, pq1, BATCH / 64, D1, bn1_g, bn1_b, s1, t1);

    // 6. z2 = BN1(z1) @ l2_w + l2_b + BN2 partials  (grid 256)
    sgemm_fused<<<dim3(D2 / 64, BATCH / 64), 64>>>(
        z1, l2_w, l2_b, s1, t1, z2, ps2, pq2, BATCH, D1, D2);

    // 7. fold BN2 partials -> s2,t2
    bn_final<<<D2 / 128, 128>>>(ps2, pq2, BATCH / 64, D2, bn2_g, bn2_b, s2, t2);

    // 8. head: BN2-apply + l3 + softmax
    head_kernel<<<BATCH / 8, 256>>>(z2, s2, t2, l3_w, l3_b, out);
}

// round 16
// speedup vs baseline: 1.0237x; 1.0237x over previous
#include <cuda_runtime.h>
#include <math.h>

typedef unsigned long long u64;

// ---------------- problem constants ----------------
#define BATCH 4096
#define NROI  90
#define TLEN  195
#define HID   20
#define FLATD (NROI*HID)     // 1800
#define KPAD  1824           // FLATD padded to multiple of 32
#define D1    512
#define D2    256
#define EPSBN 1e-5f

#define TQ   49              // ceil(195/4)
#define XST  364             // floats per tq-row: 91 rows * 4

// ---------------- packed-fp32 helpers (Blackwell f32x2 pipe) ----------------
__device__ __forceinline__ void fma2(u64& d, u64 a, u64 b) {
    asm("fma.rn.f32x2 %0, %1, %2, %0;" : "+l"(d) : "l"(a), "l"(b));
}
__device__ __forceinline__ u64 splat2(float a) {
    u64 r; asm("mov.b64 %0, {%1, %1};" : "=l"(r) : "f"(a)); return r;
}
__device__ __forceinline__ float2 u2f(u64 v) {
    float2 f; asm("mov.b64 {%0, %1}, %2;" : "=f"(f.x), "=f"(f.y) : "l"(v)); return f;
}

// gram tiles: 12 upper-triangle 32x16 tiles (i-strips {0,32,64}, j-tiles 16)
__constant__ int c_si[12] = {0,0,0,0,0,0, 32,32,32,32, 64,64};
__constant__ int c_sj[12] = {0,16,32,48,64,80, 32,48,64,80, 64,80};

// ---------------- scratch (device globals; no allocs) ----------------
__device__ float g_flat[(size_t)BATCH * KPAD];
__device__ float g_w1p[(size_t)KPAD * D1];     // padded l1_w
__device__ float g_w1q[196 * HID];             // gc1_w with zero pad row
__device__ float g_z1[(size_t)BATCH * D1];
__device__ float g_z2[(size_t)BATCH * D2];
__device__ float g_s1[D1];
__device__ float g_t1[D1];
__device__ float g_s2[D2];
__device__ float g_t2[D2];
__device__ float g_ps1[64 * D1];               // per-rowblock col sums
__device__ float g_pq1[64 * D1];
__device__ float g_ps2[64 * D2];
__device__ float g_pq2[64 * D2];

// smem layout (floats): xs | adj/w1 (overlapped) | buf | w2 | mu | rd
#define SM_XS    (TQ * XST)            // 17836
#define SM_ADJ   (NROI * 92)           // 8280 (>= 3920 for w1)
#define SM_BUF   (NROI * HID)          // 1800
#define SM_W2    (HID * HID)           // 400
#define SM_TOTAL (SM_XS + SM_ADJ + SM_BUF + SM_W2 + 96 + 96)   // 28508 fl = 114032 B

// ============================================================================
// Prep kernels
// ============================================================================
__global__ void prep_pack_w1q(const float* __restrict__ w1) {
    int i = blockIdx.x * 256 + threadIdx.x;
    if (i < 196 * HID) g_w1q[i] = (i < TLEN * HID) ? w1[i] : 0.0f;
}
__global__ void prep_pad_w1(const float* __restrict__ l1w) {
    int i = blockIdx.x * 256 + threadIdx.x;          // float4 index
    if (i < KPAD * D1 / 4) {
        int row = i / (D1 / 4);
        float4 v = make_float4(0.f, 0.f, 0.f, 0.f);
        if (row < FLATD) v = ((const float4*)l1w)[i];
        ((float4*)g_w1p)[i] = v;
    }
}
__global__ void prep_zero_flatpad() {
    int i = blockIdx.x * 256 + threadIdx.x;
    if (i < BATCH * (KPAD - FLATD)) {
        int b = i / (KPAD - FLATD);
        int c = i - b * (KPAD - FLATD);
        g_flat[(size_t)b * KPAD + FLATD + c] = 0.0f;
    }
}

// ============================================================================
// Kernel: per-sample fused GCN -> g_flat   (2 CTAs/SM; measured-best form)
// ============================================================================
__global__ void __launch_bounds__(512, 2)
gcn_kernel(const float* __restrict__ input,
           const float* __restrict__ w2)   // [20,20]
{
    extern __shared__ float sm[];
    float* xs  = sm;                       // packed x: xs[tq*364 + r*4 + comp]
    float* adj = xs  + SM_XS;              // gram/adj; FIRST used as w1 staging
    float* w1s = adj;                      // alias (w1 read before gram writes)
    float* buf = adj + SM_ADJ;             // xw, then hw
    float* w2s = buf + SM_BUF;
    float* mu  = w2s + SM_W2;              // [96]
    float* rd  = mu  + 96;                 // [96]

    const int tid  = threadIdx.x;
    const int b    = blockIdx.x;
    const int w    = tid >> 5;
    const int lane = tid & 31;

    // ---- zero the t=195 pad component for ROI rows ----
    if (tid < NROI) xs[48 * XST + tid * 4 + 3] = 0.0f;

    // ---- load x (coalesced), w1 (into adj region), w2 ----
    const float* xin = input + (size_t)b * (NROI * TLEN);
    for (int idx = tid; idx < NROI * TLEN; idx += 512) {
        int r = idx / TLEN;
        int t = idx - r * TLEN;
        xs[(t >> 2) * XST + r * 4 + (t & 3)] = xin[idx];
    }
    for (int i = tid; i < 196 * HID; i += 512) w1s[i] = g_w1q[i];
    if (tid < SM_W2) w2s[tid] = w2[tid];
    __syncthreads();

    // ---- phase A: row means + diag rsqrt + xw = x @ w1 (all read xs only) ----
    const int r3 = lane / 10;              // 0..2 (lanes 30,31 idle)
    const int hp = lane - r3 * 10;         // 0..9
    const bool act = (w < 15) && (lane < 30);

    if (w < 15) {
        for (int i = w * 6; i < w * 6 + 6; ++i) {
            float s = 0.0f, q = 0.0f;
            for (int t = lane; t < TLEN; t += 32) {
                float x = xs[(t >> 2) * XST + i * 4 + (t & 3)];
                s += x; q += x * x;
            }
            #pragma unroll
            for (int o = 16; o; o >>= 1) {
                s += __shfl_xor_sync(0xffffffffu, s, o);
                q += __shfl_xor_sync(0xffffffffu, q, o);
            }
            if (lane == 0) {
                mu[i] = s * (1.0f / (float)TLEN);
                rd[i] = rsqrtf(q - s * s * (1.0f / (float)TLEN));
            }
        }
    }
    if (act) {
        const int r0 = w * 6 + r3;
        u64 acc0 = 0ull, acc1 = 0ull;
        for (int tq = 0; tq < TQ; ++tq) {
            float4 xA = ((const float4*)(xs + tq * XST))[r0];
            float4 xB = ((const float4*)(xs + tq * XST))[r0 + 3];
            const float* wr = &w1s[tq * 80 + 2 * hp];
            u64 w0 = *(const u64*)&wr[0];
            u64 w1v = *(const u64*)&wr[20];
            u64 w2v = *(const u64*)&wr[40];
            u64 w3v = *(const u64*)&wr[60];
            fma2(acc0, splat2(xA.x), w0);  fma2(acc0, splat2(xA.y), w1v);
            fma2(acc0, splat2(xA.z), w2v); fma2(acc0, splat2(xA.w), w3v);
            fma2(acc1, splat2(xB.x), w0);  fma2(acc1, splat2(xB.y), w1v);
            fma2(acc1, splat2(xB.z), w2v); fma2(acc1, splat2(xB.w), w3v);
        }
        *(u64*)&buf[r0 * HID + 2 * hp]       = acc0;
        *(u64*)&buf[(r0 + 3) * HID + 2 * hp] = acc1;
    }
    __syncthreads();   // w1 reads done; mu/rd ready; gram may overwrite adj

    // ---- symmetric gram + fused corrcoef normalize: 12 tiles of 32x16 ----
    if (w < 12) {
        const int ii = lane >> 2;   // 0..7
        const int jj = lane & 3;    // 0..3
        const int si = c_si[w], sj = c_sj[w];
        u64 acc[4][4];
        #pragma unroll
        for (int k = 0; k < 4; k++)
            #pragma unroll
            for (int c = 0; c < 4; c++) acc[k][c] = 0ull;

        for (int tq = 0; tq < TQ; ++tq) {
            const ulonglong2* row = (const ulonglong2*)(xs + tq * XST);
            ulonglong2 b0 = row[sj + jj];
            ulonglong2 b1 = row[sj + jj + 4];
            ulonglong2 b2 = row[sj + jj + 8];
            ulonglong2 b3 = row[sj + jj + 12];
            #pragma unroll
            for (int k = 0; k < 4; k++) {
                ulonglong2 a = row[si + ii + 8 * k];
                fma2(acc[k][0], a.x, b0.x); fma2(acc[k][0], a.y, b0.y);
                fma2(acc[k][1], a.x, b1.x); fma2(acc[k][1], a.y, b1.y);
                fma2(acc[k][2], a.x, b2.x); fma2(acc[k][2], a.y, b2.y);
                fma2(acc[k][3], a.x, b3.x); fma2(acc[k][3], a.y, b3.y);
            }
        }
        // epilogue: normalize + clip + mirrored store
        float muj[4], rdj[4];
        #pragma unroll
        for (int c = 0; c < 4; c++) {
            int j = sj + jj + 4 * c;
            muj[c] = mu[j] * (float)TLEN;
            rdj[c] = rd[j];
        }
        #pragma unroll
        for (int k = 0; k < 4; k++) {
            int i = si + ii + 8 * k;
            if (i < NROI) {
                float mui = mu[i], rdi = rd[i];
                #pragma unroll
                for (int c = 0; c < 4; c++) {
                    int j = sj + jj + 4 * c;
                    if (j < NROI) {
                        float2 v = u2f(acc[k][c]);
                        float g = (v.x + v.y - mui * muj[c]) * rdi * rdj[c];
                        g = fminf(1.0f, fmaxf(-1.0f, g));
                        adj[i * 92 + j] = g;
                        adj[j * 92 + i] = g;
                    }
                }
            }
        }
    }
    __syncthreads();

    // ---- h1 = adj @ xw (into registers) ----
    u64 h1a = 0ull, h1b = 0ull;
    if (act) {
        const int n0 = w * 6 + r3;
        const float* ar0 = &adj[n0 * 92];
        const float* ar1 = &adj[(n0 + 3) * 92];
        #pragma unroll 5
        for (int m = 0; m < NROI; m += 2) {
            u64 xv0 = *(const u64*)&buf[m * HID + 2 * hp];
            u64 xv1 = *(const u64*)&buf[(m + 1) * HID + 2 * hp];
            float2 a = *(const float2*)&ar0[m];
            float2 c = *(const float2*)&ar1[m];
            fma2(h1a, splat2(a.x), xv0); fma2(h1a, splat2(a.y), xv1);
            fma2(h1b, splat2(c.x), xv0); fma2(h1b, splat2(c.y), xv1);
        }
    }
    __syncthreads();   // all xw reads done; buf can be overwritten with hw

    // ---- hw = h1 @ w2 (h1 gathered via warp shuffle) -> buf ----
    {
        u64 hw0 = 0ull, hw1 = 0ull;
        const int base = r3 * 10;
        #pragma unroll
        for (int kk = 0; kk < 10; ++kk) {
            u64 p0 = __shfl_sync(0xffffffffu, h1a, base + kk);
            u64 p1 = __shfl_sync(0xffffffffu, h1b, base + kk);
            float2 f0 = u2f(p0);
            float2 f1 = u2f(p1);
            u64 wva = *(const u64*)&w2s[(2 * kk) * HID + 2 * hp];
            u64 wvb = *(const u64*)&w2s[(2 * kk + 1) * HID + 2 * hp];
            fma2(hw0, splat2(f0.x), wva); fma2(hw0, splat2(f0.y), wvb);
            fma2(hw1, splat2(f1.x), wva); fma2(hw1, splat2(f1.y), wvb);
        }
        if (act) {
            const int n0 = w * 6 + r3;
            *(u64*)&buf[n0 * HID + 2 * hp]       = hw0;
            *(u64*)&buf[(n0 + 3) * HID + 2 * hp] = hw1;
        }
    }
    __syncthreads();

    // ---- h2 = adj @ hw -> global flat ----
    if (act) {
        const int n0 = w * 6 + r3;
        u64 acc0 = 0ull, acc1 = 0ull;
        const float* ar0 = &adj[n0 * 92];
        const float* ar1 = &adj[(n0 + 3) * 92];
        #pragma unroll 5
        for (int m = 0; m < NROI; m += 2) {
            u64 xv0 = *(const u64*)&buf[m * HID + 2 * hp];
            u64 xv1 = *(const u64*)&buf[(m + 1) * HID + 2 * hp];
            float2 a = *(const float2*)&ar0[m];
            float2 c = *(const float2*)&ar1[m];
            fma2(acc0, splat2(a.x), xv0); fma2(acc0, splat2(a.y), xv1);
            fma2(acc1, splat2(c.x), xv0); fma2(acc1, splat2(c.y), xv1);
        }
        float* dst = g_flat + (size_t)b * KPAD;
        *(u64*)&dst[n0 * HID + 2 * hp]       = acc0;
        *(u64*)&dst[(n0 + 3) * HID + 2 * hp] = acc1;
    }
}

// ============================================================================
// GEMM: 64x64x32, TM=8, TN=4, 128 threads, double-buffered (R14 measured-best).
// HAS_BN templated: BN-apply at A-load with s/t staged in smem.
// Epilogue: per-rowblock column sum/sumsq partials.
// ============================================================================
template <bool HAS_BN>
__global__ void __launch_bounds__(128)
sgemm_fused(const float* __restrict__ A, const float* __restrict__ W,
            const float* __restrict__ bias,
            const float* __restrict__ scale, const float* __restrict__ shift,
            float* __restrict__ C,
            float* __restrict__ psum, float* __restrict__ psq,
            int M, int K, int N)
{
    constexpr int BM = 64, BN = 64, BK = 32, THREADS = 128;
    constexpr int TYS = BM / 8;                  // 8
    constexpr int AF4 = BM * BK / 4 / THREADS;   // 4
    constexpr int WF4 = BK * BN / 4 / THREADS;   // 4
    __shared__ float As[2][BK][BM + 4];
    __shared__ float Bs[2][BK][BN];
    __shared__ float sS[HAS_BN ? D1 : 1];
    __shared__ float sT[HAS_BN ? D1 : 1];

    const int tid = threadIdx.x;
    const int tx  = tid % (BN / 4);
    const int ty  = tid / (BN / 4);              // 0..TYS-1
    const int bm  = blockIdx.y * BM;
    const int bn  = blockIdx.x * BN;

    if (HAS_BN) {
        for (int i = tid; i < K; i += THREADS) {
            sS[i] = scale[i];
            sT[i] = shift[i];
        }
        __syncthreads();
    }

    float4 areg[AF4], wreg[WF4];

    auto ldg_tiles = [&](int k0) {
        #pragma unroll
        for (int t = 0; t < AF4; t++) {
            int i  = tid + t * THREADS;
            int r  = i / (BK / 4);
            int c4 = (i % (BK / 4)) * 4;
            float4 v = *(const float4*)&A[(size_t)(bm + r) * K + k0 + c4];
            if (HAS_BN) {
                float4 sc = *(const float4*)&sS[k0 + c4];
                float4 sh = *(const float4*)&sT[k0 + c4];
                v.x = v.x * sc.x + sh.x; v.y = v.y * sc.y + sh.y;
                v.z = v.z * sc.z + sh.z; v.w = v.w * sc.w + sh.w;
            }
            areg[t] = v;
        }
        #pragma unroll
        for (int t = 0; t < WF4; t++) {
            int i  = tid + t * THREADS;
            int r  = i / (BN / 4);
            int c4 = (i % (BN / 4)) * 4;
            wreg[t] = *(const float4*)&W[(size_t)(k0 + r) * N + bn + c4];
        }
    };
    auto sts_tiles = [&](int s) {
        #pragma unroll
        for (int t = 0; t < AF4; t++) {
            int i  = tid + t * THREADS;
            int r  = i / (BK / 4);
            int c4 = (i % (BK / 4)) * 4;
            As[s][c4 + 0][r] = areg[t].x; As[s][c4 + 1][r] = areg[t].y;
            As[s][c4 + 2][r] = areg[t].z; As[s][c4 + 3][r] = areg[t].w;
        }
        #pragma unroll
        for (int t = 0; t < WF4; t++) {
            int i  = tid + t * THREADS;
            int r  = i / (BN / 4);
            int c4 = (i % (BN / 4)) * 4;
            *(float4*)&Bs[s][r][c4] = wreg[t];
        }
    };

    u64 acc[4][4];
    #pragma unroll
    for (int p = 0; p < 4; p++)
        #pragma unroll
        for (int j = 0; j < 4; j++) acc[p][j] = 0ull;

    ldg_tiles(0);
    sts_tiles(0);
    __syncthreads();

    const int nit = K / BK;
    for (int it = 0; it < nit; ++it) {
        const int cur = it & 1;
        if (it + 1 < nit) ldg_tiles((it + 1) * BK);

        #pragma unroll
        for (int kk = 0; kk < BK; kk++) {
            const float* arow = &As[cur][kk][ty * 8];
            u64 a0 = *(const u64*)&arow[0];
            u64 a1 = *(const u64*)&arow[2];
            u64 a2 = *(const u64*)&arow[4];
            u64 a3 = *(const u64*)&arow[6];
            float4 bv = *(const float4*)&Bs[cur][kk][tx * 4];
            u64 b0 = splat2(bv.x), b1 = splat2(bv.y);
            u64 b2 = splat2(bv.z), b3 = splat2(bv.w);
            fma2(acc[0][0], a0, b0); fma2(acc[1][0], a1, b0);
            fma2(acc[2][0], a2, b0); fma2(acc[3][0], a3, b0);
            fma2(acc[0][1], a0, b1); fma2(acc[1][1], a1, b1);
            fma2(acc[2][1], a2, b1); fma2(acc[3][1], a3, b1);
            fma2(acc[0][2], a0, b2); fma2(acc[1][2], a1, b2);
            fma2(acc[2][2], a2, b2); fma2(acc[3][2], a3, b2);
            fma2(acc[0][3], a0, b3); fma2(acc[1][3], a1, b3);
            fma2(acc[2][3], a2, b3); fma2(acc[3][3], a3, b3);
        }
        if (it + 1 < nit) sts_tiles(cur ^ 1);
        __syncthreads();
    }

    float4 bias4 = *(const float4*)&bias[bn + tx * 4];
    float cs[4] = {0.f, 0.f, 0.f, 0.f};
    float cq[4] = {0.f, 0.f, 0.f, 0.f};
    #pragma unroll
    for (int p = 0; p < 4; p++) {
        float2 c0 = u2f(acc[p][0]);
        float2 c1 = u2f(acc[p][1]);
        float2 c2 = u2f(acc[p][2]);
        float2 c3 = u2f(acc[p][3]);
        int row = bm + ty * 8 + 2 * p;
        float4 lo = make_float4(c0.x + bias4.x, c1.x + bias4.y, c2.x + bias4.z, c3.x + bias4.w);
        float4 hi = make_float4(c0.y + bias4.x, c1.y + bias4.y, c2.y + bias4.z, c3.y + bias4.w);
        *(float4*)&C[(size_t)row * N + bn + tx * 4]       = lo;
        *(float4*)&C[(size_t)(row + 1) * N + bn + tx * 4] = hi;
        cs[0] += lo.x + hi.x;  cq[0] += lo.x * lo.x + hi.x * hi.x;
        cs[1] += lo.y + hi.y;  cq[1] += lo.y * lo.y + hi.y * hi.y;
        cs[2] += lo.z + hi.z;  cq[2] += lo.z * lo.z + hi.z * hi.z;
        cs[3] += lo.w + hi.w;  cq[3] += lo.w * lo.w + hi.w * hi.w;
    }

    // ---- in-CTA column reduction over ty (reuse Bs as scratch) ----
    float* rs = (float*)Bs;          // [TYS][BN]
    float* rq = rs + TYS * BN;
    const int cb = tx * 4;
    __syncthreads();
    #pragma unroll
    for (int j = 0; j < 4; j++) {
        rs[ty * BN + cb + j] = cs[j];
        rq[ty * BN + cb + j] = cq[j];
    }
    __syncthreads();
    #pragma unroll
    for (int o = TYS / 2; o; o >>= 1) {
        if (ty < o) {
            #pragma unroll
            for (int j = 0; j < 4; j++) {
                rs[ty * BN + cb + j] += rs[(ty + o) * BN + cb + j];
                rq[ty * BN + cb + j] += rq[(ty + o) * BN + cb + j];
            }
        }
        __syncthreads();
    }
    if (ty == 0) {
        #pragma unroll
        for (int j = 0; j < 4; j++) {
            psum[(size_t)blockIdx.y * N + bn + cb + j] = rs[cb + j];
            psq [(size_t)blockIdx.y * N + bn + cb + j] = rq[cb + j];
        }
    }
}

// ============================================================================
// bn_final: fold per-rowblock partials into scale/shift
// ============================================================================
__global__ void bn_final(const float* __restrict__ psum, const float* __restrict__ psq,
                         int nparts, int N,
                         const float* __restrict__ gamma, const float* __restrict__ beta,
                         float* __restrict__ s, float* __restrict__ t)
{
    int col = blockIdx.x * 128 + threadIdx.x;
    if (col >= N) return;
    float a = 0.0f, q = 0.0f;
    for (int i = 0; i < nparts; ++i) {
        a += psum[(size_t)i * N + col];
        q += psq[(size_t)i * N + col];
    }
    float mean = a * (1.0f / (float)BATCH);
    float var  = q * (1.0f / (float)BATCH) - mean * mean;
    float sc   = gamma[col] * rsqrtf(var + EPSBN);
    s[col] = sc;
    t[col] = beta[col] - mean * sc;
}

// ============================================================================
// head — BN2-apply + [256,2] linear + softmax, warp per row
// ============================================================================
__global__ void head_kernel(const float* __restrict__ Z,
                            const float* __restrict__ s, const float* __restrict__ t,
                            const float* __restrict__ W3, const float* __restrict__ b3,
                            float* __restrict__ out)
{
    const int warp = threadIdx.x >> 5;
    const int lane = threadIdx.x & 31;
    const int row  = blockIdx.x * 8 + warp;
    const float* z = Z + (size_t)row * D2;
    float a0 = 0.0f, a1 = 0.0f;
    for (int k = lane; k < D2; k += 32) {
        float v = z[k] * s[k] + t[k];
        a0 += v * W3[k * 2 + 0];
        a1 += v * W3[k * 2 + 1];
    }
    #pragma unroll
    for (int o = 16; o; o >>= 1) {
        a0 += __shfl_xor_sync(0xffffffffu, a0, o);
        a1 += __shfl_xor_sync(0xffffffffu, a1, o);
    }
    if (lane == 0) {
        a0 += b3[0];
        a1 += b3[1];
        float m  = fmaxf(a0, a1);
        float e0 = expf(a0 - m);
        float e1 = expf(a1 - m);
        float inv = 1.0f / (e0 + e1);
        out[row * 2 + 0] = e0 * inv;
        out[row * 2 + 1] = e1 * inv;
    }
}

// ============================================================================
// launch
// ============================================================================
extern "C" void kernel_launch(void* const* d_in, const int* in_sizes, int n_in,
                              void* d_out, int out_size)
{
    const float* input = (const float*)d_in[0];
    const float* gc1_w = (const float*)d_in[1];
    const float* gc2_w = (const float*)d_in[2];
    const float* l1_w  = (const float*)d_in[3];
    const float* l1_b  = (const float*)d_in[4];
    const float* bn1_g = (const float*)d_in[5];
    const float* bn1_b = (const float*)d_in[6];
    const float* l2_w  = (const float*)d_in[7];
    const float* l2_b  = (const float*)d_in[8];
    const float* bn2_g = (const float*)d_in[9];
    const float* bn2_b = (const float*)d_in[10];
    const float* l3_w  = (const float*)d_in[11];
    const float* l3_b  = (const float*)d_in[12];
    float* out = (float*)d_out;

    float *flat, *w1p, *z1, *z2, *s1, *t1, *s2, *t2;
    float *ps1, *pq1, *ps2, *pq2;
    cudaGetSymbolAddress((void**)&flat, g_flat);
    cudaGetSymbolAddress((void**)&w1p,  g_w1p);
    cudaGetSymbolAddress((void**)&z1,   g_z1);
    cudaGetSymbolAddress((void**)&z2,   g_z2);
    cudaGetSymbolAddress((void**)&s1,   g_s1);
    cudaGetSymbolAddress((void**)&t1,   g_t1);
    cudaGetSymbolAddress((void**)&s2,   g_s2);
    cudaGetSymbolAddress((void**)&t2,   g_t2);
    cudaGetSymbolAddress((void**)&ps1,  g_ps1);
    cudaGetSymbolAddress((void**)&pq1,  g_pq1);
    cudaGetSymbolAddress((void**)&ps2,  g_ps2);
    cudaGetSymbolAddress((void**)&pq2,  g_pq2);

    const size_t smem = (size_t)SM_TOTAL * sizeof(float);   // 114,032 B
    cudaFuncSetAttribute(gcn_kernel, cudaFuncAttributeMaxDynamicSharedMemorySize, (int)smem);

    // preps
    prep_pack_w1q<<<(196 * HID + 255) / 256, 256>>>(gc1_w);
    prep_pad_w1<<<(KPAD * D1 / 4 + 255) / 256, 256>>>(l1_w);
    prep_zero_flatpad<<<(BATCH * (KPAD - FLATD) + 255) / 256, 256>>>();

    // 1. fused GCN -> g_flat [4096,1824]
    gcn_kernel<<<BATCH, 512, smem>>>(input, gc2_w);

    // 2. z1 = flat @ w1p + l1_b + BN1 partials  (64x64x32, grid 512)
    sgemm_fused<false><<<dim3(D1 / 64, BATCH / 64), 128>>>(
        flat, w1p, l1_b, nullptr, nullptr, z1, ps1, pq1, BATCH, KPAD, D1);

    // 3. fold BN1 partials -> s1,t1
    bn_final<<<D1 / 128, 128>>>(ps1, pq1, BATCH / 64, D1, bn1_g, bn1_b, s1, t1);

    // 4. z2 = BN1(z1) @ l2_w + l2_b + BN2 partials  (grid 256)
    sgemm_fused<true><<<dim3(D2 / 64, BATCH / 64), 128>>>(
        z1, l2_w, l2_b, s1, t1, z2, ps2, pq2, BATCH, D1, D2);

    // 5. fold BN2 partials -> s2,t2
    bn_final<<<D2 / 128, 128>>>(ps2, pq2, BATCH / 64, D2, bn2_g, bn2_b, s2, t2);

    // 6. head: BN2-apply + l3 + softmax
    head_kernel<<<BATCH / 8, 256>>>(z2, s2, t2, l3_w, l3_b, out);
}

// round 17
// speedup vs baseline: 1.0469x; 1.0227x over previous
#include <cuda_runtime.h>
#include <math.h>

typedef unsigned long long u64;

// ---------------- problem constants ----------------
#define BATCH 4096
#define NROI  90
#define TLEN  195
#define HID   20
#define FLATD (NROI*HID)     // 1800
#define KPAD  1824           // FLATD padded to multiple of 32
#define D1    512
#define D2    256
#define EPSBN 1e-5f

#define TQ   49              // ceil(195/4)
#define XST  364             // floats per tq-row: 91 rows * 4

// ---------------- packed-fp32 helpers (Blackwell f32x2 pipe) ----------------
__device__ __forceinline__ void fma2(u64& d, u64 a, u64 b) {
    asm("fma.rn.f32x2 %0, %1, %2, %0;" : "+l"(d) : "l"(a), "l"(b));
}
__device__ __forceinline__ u64 splat2(float a) {
    u64 r; asm("mov.b64 %0, {%1, %1};" : "=l"(r) : "f"(a)); return r;
}
__device__ __forceinline__ float2 u2f(u64 v) {
    float2 f; asm("mov.b64 {%0, %1}, %2;" : "=f"(f.x), "=f"(f.y) : "l"(v)); return f;
}

// gram tiles: 12 upper-triangle 32x16 tiles (i-strips {0,32,64}, j-tiles 16)
__constant__ int c_si[12] = {0,0,0,0,0,0, 32,32,32,32, 64,64};
__constant__ int c_sj[12] = {0,16,32,48,64,80, 32,48,64,80, 64,80};

// ---------------- scratch (device globals; no allocs) ----------------
__device__ float g_flat[(size_t)BATCH * KPAD];
__device__ float g_w1p[(size_t)KPAD * D1];     // padded l1_w
__device__ float g_w1q[196 * HID];             // gc1_w with zero pad row
__device__ float g_z1[(size_t)BATCH * D1];
__device__ float g_z2[(size_t)BATCH * D2];
__device__ float g_s1[D1];
__device__ float g_t1[D1];
__device__ float g_s2[D2];
__device__ float g_t2[D2];
__device__ float g_ps1[64 * D1];               // per-rowblock col sums
__device__ float g_pq1[64 * D1];
__device__ float g_ps2[64 * D2];
__device__ float g_pq2[64 * D2];

// smem layout (floats): xs | adj/w1 (overlapped) | buf | w2 | mu | rd
#define SM_XS    (TQ * XST)            // 17836
#define SM_ADJ   (NROI * 92)           // 8280 (>= 3920 for w1)
#define SM_BUF   (NROI * HID)          // 1800
#define SM_W2    (HID * HID)           // 400
#define SM_TOTAL (SM_XS + SM_ADJ + SM_BUF + SM_W2 + 96 + 96)   // 28508 fl = 114032 B

// ============================================================================
// Prep kernels (2 launches)
// ============================================================================
__global__ void prep_a(const float* __restrict__ w1) {
    int i = blockIdx.x * 256 + threadIdx.x;
    if (i < 196 * HID) g_w1q[i] = (i < TLEN * HID) ? w1[i] : 0.0f;
}
__global__ void prep_b(const float* __restrict__ l1w) {
    int i = blockIdx.x * 256 + threadIdx.x;
    const int NW = KPAD * D1 / 4;                  // float4 count of w1p
    if (i < NW) {
        int row = i / (D1 / 4);
        float4 v = make_float4(0.f, 0.f, 0.f, 0.f);
        if (row < FLATD) v = ((const float4*)l1w)[i];
        ((float4*)g_w1p)[i] = v;
    } else {
        int j = i - NW;                            // flat pad zeros
        if (j < BATCH * (KPAD - FLATD)) {
            int b = j / (KPAD - FLATD);
            int c = j - b * (KPAD - FLATD);
            g_flat[(size_t)b * KPAD + FLATD + c] = 0.0f;
        }
    }
}

// ============================================================================
// Kernel: per-sample fused GCN -> g_flat   (2 CTAs/SM; measured-best form)
// ============================================================================
__global__ void __launch_bounds__(512, 2)
gcn_kernel(const float* __restrict__ input,
           const float* __restrict__ w2)   // [20,20]
{
    extern __shared__ float sm[];
    float* xs  = sm;                       // packed x: xs[tq*364 + r*4 + comp]
    float* adj = xs  + SM_XS;              // gram/adj; FIRST used as w1 staging
    float* w1s = adj;                      // alias (w1 read before gram writes)
    float* buf = adj + SM_ADJ;             // xw, then hw
    float* w2s = buf + SM_BUF;
    float* mu  = w2s + SM_W2;              // [96]
    float* rd  = mu  + 96;                 // [96]

    const int tid  = threadIdx.x;
    const int b    = blockIdx.x;
    const int w    = tid >> 5;
    const int lane = tid & 31;

    // ---- zero the t=195 pad component for ROI rows ----
    if (tid < NROI) xs[48 * XST + tid * 4 + 3] = 0.0f;

    // ---- load x (coalesced), w1 (into adj region), w2 ----
    const float* xin = input + (size_t)b * (NROI * TLEN);
    for (int idx = tid; idx < NROI * TLEN; idx += 512) {
        int r = idx / TLEN;
        int t = idx - r * TLEN;
        xs[(t >> 2) * XST + r * 4 + (t & 3)] = xin[idx];
    }
    for (int i = tid; i < 196 * HID; i += 512) w1s[i] = g_w1q[i];
    if (tid < SM_W2) w2s[tid] = w2[tid];
    __syncthreads();

    // ---- phase A: row means + diag rsqrt + xw = x @ w1 (all read xs only) ----
    const int r3 = lane / 10;              // 0..2 (lanes 30,31 idle)
    const int hp = lane - r3 * 10;         // 0..9
    const bool act = (w < 15) && (lane < 30);

    if (w < 15) {
        for (int i = w * 6; i < w * 6 + 6; ++i) {
            float s = 0.0f, q = 0.0f;
            for (int t = lane; t < TLEN; t += 32) {
                float x = xs[(t >> 2) * XST + i * 4 + (t & 3)];
                s += x; q += x * x;
            }
            #pragma unroll
            for (int o = 16; o; o >>= 1) {
                s += __shfl_xor_sync(0xffffffffu, s, o);
                q += __shfl_xor_sync(0xffffffffu, q, o);
            }
            if (lane == 0) {
                mu[i] = s * (1.0f / (float)TLEN);
                rd[i] = rsqrtf(q - s * s * (1.0f / (float)TLEN));
            }
        }
    }
    if (act) {
        const int r0 = w * 6 + r3;
        u64 acc0 = 0ull, acc1 = 0ull;
        for (int tq = 0; tq < TQ; ++tq) {
            float4 xA = ((const float4*)(xs + tq * XST))[r0];
            float4 xB = ((const float4*)(xs + tq * XST))[r0 + 3];
            const float* wr = &w1s[tq * 80 + 2 * hp];
            u64 w0 = *(const u64*)&wr[0];
            u64 w1v = *(const u64*)&wr[20];
            u64 w2v = *(const u64*)&wr[40];
            u64 w3v = *(const u64*)&wr[60];
            fma2(acc0, splat2(xA.x), w0);  fma2(acc0, splat2(xA.y), w1v);
            fma2(acc0, splat2(xA.z), w2v); fma2(acc0, splat2(xA.w), w3v);
            fma2(acc1, splat2(xB.x), w0);  fma2(acc1, splat2(xB.y), w1v);
            fma2(acc1, splat2(xB.z), w2v); fma2(acc1, splat2(xB.w), w3v);
        }
        *(u64*)&buf[r0 * HID + 2 * hp]       = acc0;
        *(u64*)&buf[(r0 + 3) * HID + 2 * hp] = acc1;
    }
    __syncthreads();   // w1 reads done; mu/rd ready; gram may overwrite adj

    // ---- symmetric gram + fused corrcoef normalize: 12 tiles of 32x16 ----
    if (w < 12) {
        const int ii = lane >> 2;   // 0..7
        const int jj = lane & 3;    // 0..3
        const int si = c_si[w], sj = c_sj[w];
        u64 acc[4][4];
        #pragma unroll
        for (int k = 0; k < 4; k++)
            #pragma unroll
            for (int c = 0; c < 4; c++) acc[k][c] = 0ull;

        for (int tq = 0; tq < TQ; ++tq) {
            const ulonglong2* row = (const ulonglong2*)(xs + tq * XST);
            ulonglong2 b0 = row[sj + jj];
            ulonglong2 b1 = row[sj + jj + 4];
            ulonglong2 b2 = row[sj + jj + 8];
            ulonglong2 b3 = row[sj + jj + 12];
            #pragma unroll
            for (int k = 0; k < 4; k++) {
                ulonglong2 a = row[si + ii + 8 * k];
                fma2(acc[k][0], a.x, b0.x); fma2(acc[k][0], a.y, b0.y);
                fma2(acc[k][1], a.x, b1.x); fma2(acc[k][1], a.y, b1.y);
                fma2(acc[k][2], a.x, b2.x); fma2(acc[k][2], a.y, b2.y);
                fma2(acc[k][3], a.x, b3.x); fma2(acc[k][3], a.y, b3.y);
            }
        }
        // epilogue: normalize + clip + mirrored store
        float muj[4], rdj[4];
        #pragma unroll
        for (int c = 0; c < 4; c++) {
            int j = sj + jj + 4 * c;
            muj[c] = mu[j] * (float)TLEN;
            rdj[c] = rd[j];
        }
        #pragma unroll
        for (int k = 0; k < 4; k++) {
            int i = si + ii + 8 * k;
            if (i < NROI) {
                float mui = mu[i], rdi = rd[i];
                #pragma unroll
                for (int c = 0; c < 4; c++) {
                    int j = sj + jj + 4 * c;
                    if (j < NROI) {
                        float2 v = u2f(acc[k][c]);
                        float g = (v.x + v.y - mui * muj[c]) * rdi * rdj[c];
                        g = fminf(1.0f, fmaxf(-1.0f, g));
                        adj[i * 92 + j] = g;
                        adj[j * 92 + i] = g;
                    }
                }
            }
        }
    }
    __syncthreads();

    // ---- h1 = adj @ xw (into registers) ----
    u64 h1a = 0ull, h1b = 0ull;
    if (act) {
        const int n0 = w * 6 + r3;
        const float* ar0 = &adj[n0 * 92];
        const float* ar1 = &adj[(n0 + 3) * 92];
        #pragma unroll 5
        for (int m = 0; m < NROI; m += 2) {
            u64 xv0 = *(const u64*)&buf[m * HID + 2 * hp];
            u64 xv1 = *(const u64*)&buf[(m + 1) * HID + 2 * hp];
            float2 a = *(const float2*)&ar0[m];
            float2 c = *(const float2*)&ar1[m];
            fma2(h1a, splat2(a.x), xv0); fma2(h1a, splat2(a.y), xv1);
            fma2(h1b, splat2(c.x), xv0); fma2(h1b, splat2(c.y), xv1);
        }
    }
    __syncthreads();   // all xw reads done; buf can be overwritten with hw

    // ---- hw = h1 @ w2 (h1 gathered via warp shuffle) -> buf ----
    {
        u64 hw0 = 0ull, hw1 = 0ull;
        const int base = r3 * 10;
        #pragma unroll
        for (int kk = 0; kk < 10; ++kk) {
            u64 p0 = __shfl_sync(0xffffffffu, h1a, base + kk);
            u64 p1 = __shfl_sync(0xffffffffu, h1b, base + kk);
            float2 f0 = u2f(p0);
            float2 f1 = u2f(p1);
            u64 wva = *(const u64*)&w2s[(2 * kk) * HID + 2 * hp];
            u64 wvb = *(const u64*)&w2s[(2 * kk + 1) * HID + 2 * hp];
            fma2(hw0, splat2(f0.x), wva); fma2(hw0, splat2(f0.y), wvb);
            fma2(hw1, splat2(f1.x), wva); fma2(hw1, splat2(f1.y), wvb);
        }
        if (act) {
            const int n0 = w * 6 + r3;
            *(u64*)&buf[n0 * HID + 2 * hp]       = hw0;
            *(u64*)&buf[(n0 + 3) * HID + 2 * hp] = hw1;
        }
    }
    __syncthreads();

    // ---- h2 = adj @ hw -> global flat ----
    if (act) {
        const int n0 = w * 6 + r3;
        u64 acc0 = 0ull, acc1 = 0ull;
        const float* ar0 = &adj[n0 * 92];
        const float* ar1 = &adj[(n0 + 3) * 92];
        #pragma unroll 5
        for (int m = 0; m < NROI; m += 2) {
            u64 xv0 = *(const u64*)&buf[m * HID + 2 * hp];
            u64 xv1 = *(const u64*)&buf[(m + 1) * HID + 2 * hp];
            float2 a = *(const float2*)&ar0[m];
            float2 c = *(const float2*)&ar1[m];
            fma2(acc0, splat2(a.x), xv0); fma2(acc0, splat2(a.y), xv1);
            fma2(acc1, splat2(c.x), xv0); fma2(acc1, splat2(c.y), xv1);
        }
        float* dst = g_flat + (size_t)b * KPAD;
        *(u64*)&dst[n0 * HID + 2 * hp]       = acc0;
        *(u64*)&dst[(n0 + 3) * HID + 2 * hp] = acc1;
    }
}

// ============================================================================
// GEMM: 64x64x32, TM=8, TN=4, 128 threads, double-buffered (measured-best).
// C = A' @ W + bias  (A' = A*scale[k]+shift[k] if scale != null)
// Epilogue: per-rowblock column sum/sumsq partials -> psum/psq[by*N + col]
// ============================================================================
__global__ void __launch_bounds__(128)
sgemm_fused(const float* __restrict__ A, const float* __restrict__ W,
            const float* __restrict__ bias,
            const float* __restrict__ scale, const float* __restrict__ shift,
            float* __restrict__ C,
            float* __restrict__ psum, float* __restrict__ psq,
            int M, int K, int N)
{
    constexpr int BM = 64, BN = 64, BK = 32, THREADS = 128;
    constexpr int TYS = BM / 8;                  // 8
    constexpr int AF4 = BM * BK / 4 / THREADS;   // 4
    constexpr int WF4 = BK * BN / 4 / THREADS;   // 4
    __shared__ float As[2][BK][BM + 4];
    __shared__ float Bs[2][BK][BN];

    const int tid = threadIdx.x;
    const int tx  = tid % (BN / 4);
    const int ty  = tid / (BN / 4);              // 0..TYS-1
    const int bm  = blockIdx.y * BM;
    const int bn  = blockIdx.x * BN;

    float4 areg[AF4], wreg[WF4];

    auto ldg_tiles = [&](int k0) {
        #pragma unroll
        for (int t = 0; t < AF4; t++) {
            int i  = tid + t * THREADS;
            int r  = i / (BK / 4);
            int c4 = (i % (BK / 4)) * 4;
            float4 v = *(const float4*)&A[(size_t)(bm + r) * K + k0 + c4];
            if (scale) {
                float4 sc = *(const float4*)&scale[k0 + c4];
                float4 sh = *(const float4*)&shift[k0 + c4];
                v.x = v.x * sc.x + sh.x; v.y = v.y * sc.y + sh.y;
                v.z = v.z * sc.z + sh.z; v.w = v.w * sc.w + sh.w;
            }
            areg[t] = v;
        }
        #pragma unroll
        for (int t = 0; t < WF4; t++) {
            int i  = tid + t * THREADS;
            int r  = i / (BN / 4);
            int c4 = (i % (BN / 4)) * 4;
            wreg[t] = *(const float4*)&W[(size_t)(k0 + r) * N + bn + c4];
        }
    };
    auto sts_tiles = [&](int s) {
        #pragma unroll
        for (int t = 0; t < AF4; t++) {
            int i  = tid + t * THREADS;
            int r  = i / (BK / 4);
            int c4 = (i % (BK / 4)) * 4;
            As[s][c4 + 0][r] = areg[t].x; As[s][c4 + 1][r] = areg[t].y;
            As[s][c4 + 2][r] = areg[t].z; As[s][c4 + 3][r] = areg[t].w;
        }
        #pragma unroll
        for (int t = 0; t < WF4; t++) {
            int i  = tid + t * THREADS;
            int r  = i / (BN / 4);
            int c4 = (i % (BN / 4)) * 4;
            *(float4*)&Bs[s][r][c4] = wreg[t];
        }
    };

    u64 acc[4][4];
    #pragma unroll
    for (int p = 0; p < 4; p++)
        #pragma unroll
        for (int j = 0; j < 4; j++) acc[p][j] = 0ull;

    ldg_tiles(0);
    sts_tiles(0);
    __syncthreads();

    const int nit = K / BK;
    for (int it = 0; it < nit; ++it) {
        const int cur = it & 1;
        if (it + 1 < nit) ldg_tiles((it + 1) * BK);

        #pragma unroll
        for (int kk = 0; kk < BK; kk++) {
            const float* arow = &As[cur][kk][ty * 8];
            u64 a0 = *(const u64*)&arow[0];
            u64 a1 = *(const u64*)&arow[2];
            u64 a2 = *(const u64*)&arow[4];
            u64 a3 = *(const u64*)&arow[6];
            float4 bv = *(const float4*)&Bs[cur][kk][tx * 4];
            u64 b0 = splat2(bv.x), b1 = splat2(bv.y);
            u64 b2 = splat2(bv.z), b3 = splat2(bv.w);
            fma2(acc[0][0], a0, b0); fma2(acc[1][0], a1, b0);
            fma2(acc[2][0], a2, b0); fma2(acc[3][0], a3, b0);
            fma2(acc[0][1], a0, b1); fma2(acc[1][1], a1, b1);
            fma2(acc[2][1], a2, b1); fma2(acc[3][1], a3, b1);
            fma2(acc[0][2], a0, b2); fma2(acc[1][2], a1, b2);
            fma2(acc[2][2], a2, b2); fma2(acc[3][2], a3, b2);
            fma2(acc[0][3], a0, b3); fma2(acc[1][3], a1, b3);
            fma2(acc[2][3], a2, b3); fma2(acc[3][3], a3, b3);
        }
        if (it + 1 < nit) sts_tiles(cur ^ 1);
        __syncthreads();
    }

    float4 bias4 = *(const float4*)&bias[bn + tx * 4];
    float cs[4] = {0.f, 0.f, 0.f, 0.f};
    float cq[4] = {0.f, 0.f, 0.f, 0.f};
    #pragma unroll
    for (int p = 0; p < 4; p++) {
        float2 c0 = u2f(acc[p][0]);
        float2 c1 = u2f(acc[p][1]);
        float2 c2 = u2f(acc[p][2]);
        float2 c3 = u2f(acc[p][3]);
        int row = bm + ty * 8 + 2 * p;
        float4 lo = make_float4(c0.x + bias4.x, c1.x + bias4.y, c2.x + bias4.z, c3.x + bias4.w);
        float4 hi = make_float4(c0.y + bias4.x, c1.y + bias4.y, c2.y + bias4.z, c3.y + bias4.w);
        *(float4*)&C[(size_t)row * N + bn + tx * 4]       = lo;
        *(float4*)&C[(size_t)(row + 1) * N + bn + tx * 4] = hi;
        cs[0] += lo.x + hi.x;  cq[0] += lo.x * lo.x + hi.x * hi.x;
        cs[1] += lo.y + hi.y;  cq[1] += lo.y * lo.y + hi.y * hi.y;
        cs[2] += lo.z + hi.z;  cq[2] += lo.z * lo.z + hi.z * hi.z;
        cs[3] += lo.w + hi.w;  cq[3] += lo.w * lo.w + hi.w * hi.w;
    }

    // ---- in-CTA column reduction over ty (reuse Bs as scratch) ----
    float* rs = (float*)Bs;          // [TYS][BN]
    float* rq = rs + TYS * BN;
    const int cb = tx * 4;
    __syncthreads();
    #pragma unroll
    for (int j = 0; j < 4; j++) {
        rs[ty * BN + cb + j] = cs[j];
        rq[ty * BN + cb + j] = cq[j];
    }
    __syncthreads();
    #pragma unroll
    for (int o = TYS / 2; o; o >>= 1) {
        if (ty < o) {
            #pragma unroll
            for (int j = 0; j < 4; j++) {
                rs[ty * BN + cb + j] += rs[(ty + o) * BN + cb + j];
                rq[ty * BN + cb + j] += rq[(ty + o) * BN + cb + j];
            }
        }
        __syncthreads();
    }
    if (ty == 0) {
        #pragma unroll
        for (int j = 0; j < 4; j++) {
            psum[(size_t)blockIdx.y * N + bn + cb + j] = rs[cb + j];
            psq [(size_t)blockIdx.y * N + bn + cb + j] = rq[cb + j];
        }
    }
}

// ============================================================================
// bn_final: fold per-rowblock partials into scale/shift
// ============================================================================
__global__ void bn_final(const float* __restrict__ psum, const float* __restrict__ psq,
                         int nparts, int N,
                         const float* __restrict__ gamma, const float* __restrict__ beta,
                         float* __restrict__ s, float* __restrict__ t)
{
    int col = blockIdx.x * 128 + threadIdx.x;
    if (col >= N) return;
    float a = 0.0f, q = 0.0f;
    for (int i = 0; i < nparts; ++i) {
        a += psum[(size_t)i * N + col];
        q += psq[(size_t)i * N + col];
    }
    float mean = a * (1.0f / (float)BATCH);
    float var  = q * (1.0f / (float)BATCH) - mean * mean;
    float sc   = gamma[col] * rsqrtf(var + EPSBN);
    s[col] = sc;
    t[col] = beta[col] - mean * sc;
}

// ============================================================================
// head — BN2-apply + [256,2] linear + softmax, warp per row
// ============================================================================
__global__ void head_kernel(const float* __restrict__ Z,
                            const float* __restrict__ s, const float* __restrict__ t,
                            const float* __restrict__ W3, const float* __restrict__ b3,
                            float* __restrict__ out)
{
    const int warp = threadIdx.x >> 5;
    const int lane = threadIdx.x & 31;
    const int row  = blockIdx.x * 8 + warp;
    const float* z = Z + (size_t)row * D2;
    float a0 = 0.0f, a1 = 0.0f;
    for (int k = lane; k < D2; k += 32) {
        float v = z[k] * s[k] + t[k];
        a0 += v * W3[k * 2 + 0];
        a1 += v * W3[k * 2 + 1];
    }
    #pragma unroll
    for (int o = 16; o; o >>= 1) {
        a0 += __shfl_xor_sync(0xffffffffu, a0, o);
        a1 += __shfl_xor_sync(0xffffffffu, a1, o);
    }
    if (lane == 0) {
        a0 += b3[0];
        a1 += b3[1];
        float m  = fmaxf(a0, a1);
        float e0 = expf(a0 - m);
        float e1 = expf(a1 - m);
        float inv = 1.0f / (e0 + e1);
        out[row * 2 + 0] = e0 * inv;
        out[row * 2 + 1] = e1 * inv;
    }
}

// ============================================================================
// launch
// ============================================================================
extern "C" void kernel_launch(void* const* d_in, const int* in_sizes, int n_in,
                              void* d_out, int out_size)
{
    const float* input = (const float*)d_in[0];
    const float* gc1_w = (const float*)d_in[1];
    const float* gc2_w = (const float*)d_in[2];
    const float* l1_w  = (const float*)d_in[3];
    const float* l1_b  = (const float*)d_in[4];
    const float* bn1_g = (const float*)d_in[5];
    const float* bn1_b = (const float*)d_in[6];
    const float* l2_w  = (const float*)d_in[7];
    const float* l2_b  = (const float*)d_in[8];
    const float* bn2_g = (const float*)d_in[9];
    const float* bn2_b = (const float*)d_in[10];
    const float* l3_w  = (const float*)d_in[11];
    const float* l3_b  = (const float*)d_in[12];
    float* out = (float*)d_out;

    float *flat, *w1p, *z1, *z2, *s1, *t1, *s2, *t2;
    float *ps1, *pq1, *ps2, *pq2;
    cudaGetSymbolAddress((void**)&flat, g_flat);
    cudaGetSymbolAddress((void**)&w1p,  g_w1p);
    cudaGetSymbolAddress((void**)&z1,   g_z1);
    cudaGetSymbolAddress((void**)&z2,   g_z2);
    cudaGetSymbolAddress((void**)&s1,   g_s1);
    cudaGetSymbolAddress((void**)&t1,   g_t1);
    cudaGetSymbolAddress((void**)&s2,   g_s2);
    cudaGetSymbolAddress((void**)&t2,   g_t2);
    cudaGetSymbolAddress((void**)&ps1,  g_ps1);
    cudaGetSymbolAddress((void**)&pq1,  g_pq1);
    cudaGetSymbolAddress((void**)&ps2,  g_ps2);
    cudaGetSymbolAddress((void**)&pq2,  g_pq2);

    const size_t smem = (size_t)SM_TOTAL * sizeof(float);   // 114,032 B
    cudaFuncSetAttribute(gcn_kernel, cudaFuncAttributeMaxDynamicSharedMemorySize, (int)smem);

    // preps (2 launches)
    prep_a<<<(196 * HID + 255) / 256, 256>>>(gc1_w);
    {
        int total = KPAD * D1 / 4 + BATCH * (KPAD - FLATD);
        prep_b<<<(total + 255) / 256, 256>>>(l1_w);
    }

    // fused GCN -> g_flat [4096,1824]
    gcn_kernel<<<BATCH, 512, smem>>>(input, gc2_w);

    // z1 = flat @ w1p + l1_b + BN1 partials  (64x64x32, TM=8, grid 512)
    sgemm_fused<<<dim3(D1 / 64, BATCH / 64), 128>>>(
        flat, w1p, l1_b, nullptr, nullptr, z1, ps1, pq1, BATCH, KPAD, D1);

    // fold BN1 partials -> s1,t1
    bn_final<<<D1 / 128, 128>>>(ps1, pq1, BATCH / 64, D1, bn1_g, bn1_b, s1, t1);

    // z2 = BN1(z1) @ l2_w + l2_b + BN2 partials  (grid 256)
    sgemm_fused<<<dim3(D2 / 64, BATCH / 64), 128>>>(
        z1, l2_w, l2_b, s1, t1, z2, ps2, pq2, BATCH, D1, D2);

    // fold BN2 partials -> s2,t2
    bn_final<<<D2 / 128, 128>>>(ps2, pq2, BATCH / 64, D2, bn2_g, bn2_b, s2, t2);

    // head: BN2-apply + l3 + softmax
    head_kernel<<<BATCH / 8, 256>>>(z2, s2, t2, l3_w, l3_b, out);
}